// round 2
// baseline (speedup 1.0000x reference)
#include <cuda_runtime.h>
#include <cuda_bf16.h>
#include <math.h>

// Problem constants
#define BATCH 8192
#define SEQ   4
#define CDIM  1024
#define HEADS 16
#define HDIM  64
#define PDIM  4
#define MROWS (BATCH * SEQ)        // 32768
#define QKVC  (3 * CDIM)           // 3072
#define OUT_ELEMS ((size_t)MROWS * CDIM)        // 33,554,432
#define SEL_ELEMS ((size_t)BATCH * HEADS * HEADS) // 2,097,152

// -------- global scratch (allocation-free per harness rules) --------
__device__ float g_qkv[(size_t)MROWS * QKVC];   // ~402 MB
__device__ float g_ho [(size_t)MROWS * CDIM];   // ~134 MB

// ======================= FP32 tiled GEMM (f32x2 FMA) =======================
// C[M,N] = A[M,K] * B  (+bias).  TRANSB=false: B is [K,N] row-major.
// TRANSB=true: B is [N,K] row-major (i.e. C = A * B^T).
#define BM 128
#define BN 128
#define BK 16
#define SPAD 4

__device__ __forceinline__ void ffma2(unsigned long long &c,
                                      unsigned long long a,
                                      unsigned long long b) {
    asm("fma.rn.f32x2 %0, %1, %2, %0;" : "+l"(c) : "l"(a), "l"(b));
}
__device__ __forceinline__ unsigned long long bcast2(float a) {
    unsigned long long r;
    asm("mov.b64 %0, {%1, %1};" : "=l"(r) : "f"(a));
    return r;
}

template<bool TRANSB, bool BIAS>
__global__ __launch_bounds__(256, 2) void gemm_t(
    const float* __restrict__ A, const float* __restrict__ B,
    const float* __restrict__ bias, float* __restrict__ C,
    int M, int N, int K)
{
    __shared__ float As[BK][BM + SPAD];
    __shared__ float Bs[BK][BN + SPAD];
    const int tid = threadIdx.x;
    const int m0 = blockIdx.y * BM;
    const int n0 = blockIdx.x * BN;
    const int tm = (tid >> 4) << 3;
    const int tn = (tid & 15) << 3;

    unsigned long long acc[8][4];
#pragma unroll
    for (int i = 0; i < 8; i++)
#pragma unroll
        for (int j = 0; j < 4; j++) acc[i][j] = 0ull;

    for (int kt = 0; kt < K; kt += BK) {
        // ---- load A tile [BM x BK], store transposed As[k][m]
#pragma unroll
        for (int i = 0; i < 2; i++) {
            int f = tid + i * 256;
            int r = f >> 2, c4 = (f & 3) << 2;
            float4 av = *reinterpret_cast<const float4*>(
                &A[(size_t)(m0 + r) * K + kt + c4]);
            As[c4 + 0][r] = av.x; As[c4 + 1][r] = av.y;
            As[c4 + 2][r] = av.z; As[c4 + 3][r] = av.w;
        }
        // ---- load B tile
        if (!TRANSB) {
#pragma unroll
            for (int i = 0; i < 2; i++) {
                int f = tid + i * 256;
                int r = f >> 5, c4 = (f & 31) << 2;
                *reinterpret_cast<float4*>(&Bs[r][c4]) =
                    *reinterpret_cast<const float4*>(
                        &B[(size_t)(kt + r) * N + n0 + c4]);
            }
        } else {
#pragma unroll
            for (int i = 0; i < 2; i++) {
                int f = tid + i * 256;
                int r = f >> 2, c4 = (f & 3) << 2;  // r = n, c4 = k
                float4 bv = *reinterpret_cast<const float4*>(
                    &B[(size_t)(n0 + r) * K + kt + c4]);
                Bs[c4 + 0][r] = bv.x; Bs[c4 + 1][r] = bv.y;
                Bs[c4 + 2][r] = bv.z; Bs[c4 + 3][r] = bv.w;
            }
        }
        __syncthreads();
#pragma unroll
        for (int k = 0; k < BK; k++) {
            float4 a0 = *reinterpret_cast<const float4*>(&As[k][tm]);
            float4 a1 = *reinterpret_cast<const float4*>(&As[k][tm + 4]);
            ulonglong2 b0 = *reinterpret_cast<const ulonglong2*>(&Bs[k][tn]);
            ulonglong2 b1 = *reinterpret_cast<const ulonglong2*>(&Bs[k][tn + 4]);
            unsigned long long bb0 = b0.x, bb1 = b0.y, bb2 = b1.x, bb3 = b1.y;
            float aa[8] = {a0.x, a0.y, a0.z, a0.w, a1.x, a1.y, a1.z, a1.w};
#pragma unroll
            for (int i = 0; i < 8; i++) {
                unsigned long long a2 = bcast2(aa[i]);
                ffma2(acc[i][0], a2, bb0);
                ffma2(acc[i][1], a2, bb1);
                ffma2(acc[i][2], a2, bb2);
                ffma2(acc[i][3], a2, bb3);
            }
        }
        __syncthreads();
    }

    // ---- epilogue
#pragma unroll
    for (int i = 0; i < 8; i++) {
        float o[8];
#pragma unroll
        for (int j = 0; j < 4; j++) {
            uint2 u;
            asm("mov.b64 {%0, %1}, %2;" : "=r"(u.x), "=r"(u.y) : "l"(acc[i][j]));
            o[2 * j]     = __uint_as_float(u.x);
            o[2 * j + 1] = __uint_as_float(u.y);
        }
        if (BIAS) {
#pragma unroll
            for (int j = 0; j < 8; j++) o[j] += bias[n0 + tn + j];
        }
        size_t off = (size_t)(m0 + tm + i) * N + n0 + tn;
        *reinterpret_cast<float4*>(&C[off])     = make_float4(o[0], o[1], o[2], o[3]);
        *reinterpret_cast<float4*>(&C[off + 4]) = make_float4(o[4], o[5], o[6], o[7]);
    }
}

// ======================= per-batch attention kernel =======================
// One block per batch element. 512 threads = 16 warps; warp h = head h.
// Each lane owns 2 of the 64 head-dim channels.
__global__ __launch_bounds__(512) void attn_kernel(
    const float* __restrict__ qkv,
    const float* __restrict__ W_E, const float* __restrict__ W_F,
    float* __restrict__ ho, float* __restrict__ sel_out)
{
    __shared__ float s[SEQ * QKVC];  // 48 KB
    const int b = blockIdx.x;
    const int tid = threadIdx.x;

    // load the 4 qkv rows of this batch (3072 float4)
    const float4* src = reinterpret_cast<const float4*>(qkv + (size_t)b * SEQ * QKVC);
    float4* dst = reinterpret_cast<float4*>(s);
#pragma unroll
    for (int i = 0; i < 6; i++) dst[tid + i * 512] = src[tid + i * 512];
    __syncthreads();

    const int h = tid >> 5, lane = tid & 31;
    const int d0 = lane << 1;

    float q[SEQ][2], kk[SEQ][2], vv[SEQ][2];
#pragma unroll
    for (int n = 0; n < SEQ; n++) {
#pragma unroll
        for (int j = 0; j < 2; j++) {
            q[n][j]  = s[n * QKVC +          h * HDIM + d0 + j] * 0.125f;  // D^-0.5
            kk[n][j] = s[n * QKVC + CDIM +   h * HDIM + d0 + j];
            vv[n][j] = s[n * QKVC + 2*CDIM + h * HDIM + d0 + j];
        }
    }

    float wE[16], wF[16];
#pragma unroll
    for (int i = 0; i < 16; i++) { wE[i] = __ldg(&W_E[i]); wF[i] = __ldg(&W_F[i]); }

    // Linformer E/F projection along sequence: [P x 2] per lane
    float klow[PDIM][2], vlow[PDIM][2];
#pragma unroll
    for (int p = 0; p < PDIM; p++)
#pragma unroll
        for (int j = 0; j < 2; j++) {
            klow[p][j] = wE[p*4+0]*kk[0][j] + wE[p*4+1]*kk[1][j]
                       + wE[p*4+2]*kk[2][j] + wE[p*4+3]*kk[3][j];
            vlow[p][j] = wF[p*4+0]*vv[0][j] + wF[p*4+1]*vv[1][j]
                       + wF[p*4+2]*vv[2][j] + wF[p*4+3]*vv[3][j];
        }

    // logits [N x P]: dot over d (64) via butterfly reduce
    float attn[SEQ][PDIM];
#pragma unroll
    for (int n = 0; n < SEQ; n++)
#pragma unroll
        for (int p = 0; p < PDIM; p++) {
            float part = q[n][0]*klow[p][0] + q[n][1]*klow[p][1];
#pragma unroll
            for (int o = 16; o > 0; o >>= 1)
                part += __shfl_xor_sync(0xffffffffu, part, o);
            attn[n][p] = part;
        }

    // softmax over p
#pragma unroll
    for (int n = 0; n < SEQ; n++) {
        float mx = fmaxf(fmaxf(attn[n][0], attn[n][1]), fmaxf(attn[n][2], attn[n][3]));
        float e0 = expf(attn[n][0]-mx), e1 = expf(attn[n][1]-mx);
        float e2 = expf(attn[n][2]-mx), e3 = expf(attn[n][3]-mx);
        float inv = 1.0f / (e0 + e1 + e2 + e3);
        attn[n][0] = e0*inv; attn[n][1] = e1*inv; attn[n][2] = e2*inv; attn[n][3] = e3*inv;
    }

    // out[n][d] = attn @ v_low ; write merged-head layout
#pragma unroll
    for (int n = 0; n < SEQ; n++) {
        float o0 = attn[n][0]*vlow[0][0] + attn[n][1]*vlow[1][0]
                 + attn[n][2]*vlow[2][0] + attn[n][3]*vlow[3][0];
        float o1 = attn[n][0]*vlow[0][1] + attn[n][1]*vlow[1][1]
                 + attn[n][2]*vlow[2][1] + attn[n][3]*vlow[3][1];
        *reinterpret_cast<float2*>(
            &ho[(size_t)(b * SEQ + n) * CDIM + h * HDIM + d0]) = make_float2(o0, o1);
    }

    // attn_sel[h][g] = sigmoid( sum_d q_scaled[h, n=1, d] * k[g, n=2, d] )
    float selval = 0.0f;
#pragma unroll
    for (int g = 0; g < HEADS; g++) {
        float part = q[1][0] * s[2*QKVC + CDIM + g*HDIM + d0]
                   + q[1][1] * s[2*QKVC + CDIM + g*HDIM + d0 + 1];
#pragma unroll
        for (int o = 16; o > 0; o >>= 1)
            part += __shfl_xor_sync(0xffffffffu, part, o);
        if (lane == g) selval = part;
    }
    if (lane < HEADS)
        sel_out[(size_t)b * HEADS * HEADS + h * HEADS + lane] =
            1.0f / (1.0f + expf(-selval));
}

// ======================= launch =======================
extern "C" void kernel_launch(void* const* d_in, const int* in_sizes, int n_in,
                              void* d_out, int out_size) {
    const float* x      = (const float*)d_in[0];
    const float* W_qkv  = (const float*)d_in[1];
    const float* W_proj = (const float*)d_in[2];
    const float* b_proj = (const float*)d_in[3];
    const float* W_E    = (const float*)d_in[4];
    const float* W_F    = (const float*)d_in[5];
    float* out = (float*)d_out;
    float* sel = out + OUT_ELEMS;

    static float* qkv_ptr = nullptr;
    static float* ho_ptr  = nullptr;
    if (!qkv_ptr) {
        cudaGetSymbolAddress((void**)&qkv_ptr, g_qkv);
        cudaGetSymbolAddress((void**)&ho_ptr,  g_ho);
    }

    // 1) qkv = x @ W_qkv   [32768,1024]x[1024,3072]
    dim3 g1(QKVC / BN, MROWS / BM);
    gemm_t<false, false><<<g1, 256>>>(x, W_qkv, nullptr, qkv_ptr,
                                      MROWS, QKVC, CDIM);
    // 2) attention middle + sel gate
    attn_kernel<<<BATCH, 512>>>(qkv_ptr, W_E, W_F, ho_ptr, sel);
    // 3) out = ho @ W_proj^T + b_proj   [32768,1024]x[1024,1024]^T
    dim3 g3(CDIM / BN, MROWS / BM);
    gemm_t<true, true><<<g3, 256>>>(ho_ptr, W_proj, b_proj, out,
                                    MROWS, CDIM, CDIM);
}

// round 4
// speedup vs baseline: 5.8725x; 5.8725x over previous
#include <cuda_runtime.h>
#include <cuda_fp16.h>
#include <math.h>
#include <stdint.h>

// Problem constants
#define BATCH 8192
#define SEQ   4
#define CDIM  1024
#define HEADS 16
#define HDIM  64
#define PDIM  4
#define MROWS (BATCH * SEQ)        // 32768
#define QKVC  (3 * CDIM)           // 3072
#define OUT_ELEMS ((size_t)MROWS * CDIM)
#define SEL_ELEMS ((size_t)BATCH * HEADS * HEADS)

// -------- global scratch (allocation-free per harness rules) --------
__device__ __half g_xh [(size_t)MROWS * CDIM];   // x in fp16, 67MB
__device__ __half g_wqh[(size_t)QKVC * CDIM];    // W_qkv^T fp16 [3072,1024], 6.3MB
__device__ __half g_wph[(size_t)CDIM * CDIM];    // W_proj fp16 [1024,1024], 2.1MB
__device__ float  g_qkv[(size_t)MROWS * QKVC];   // qkv f32, 402MB
__device__ __half g_hoh[(size_t)MROWS * CDIM];   // attention out fp16, 67MB

// ======================= helpers =======================
__device__ __forceinline__ uint32_t smem_u32(const void* p) {
    return (uint32_t)__cvta_generic_to_shared(p);
}
__device__ __forceinline__ void cp16(uint32_t dst, const void* src) {
    asm volatile("cp.async.cg.shared.global [%0], [%1], 16;" :: "r"(dst), "l"(src));
}
#define CP_COMMIT()  asm volatile("cp.async.commit_group;" ::: "memory")
#define CP_WAIT1()   asm volatile("cp.async.wait_group 1;" ::: "memory")

#define LDSM4(r, a) \
    asm volatile("ldmatrix.sync.aligned.m8n8.x4.shared.b16 {%0,%1,%2,%3}, [%4];" \
        : "=r"((r)[0]), "=r"((r)[1]), "=r"((r)[2]), "=r"((r)[3]) : "r"(a))

#define MMA16816(d, a, b0, b1) \
    asm volatile("mma.sync.aligned.m16n8k16.row.col.f32.f16.f16.f32 " \
        "{%0,%1,%2,%3}, {%4,%5,%6,%7}, {%8,%9}, {%0,%1,%2,%3};" \
        : "+f"((d)[0]), "+f"((d)[1]), "+f"((d)[2]), "+f"((d)[3]) \
        : "r"((a)[0]), "r"((a)[1]), "r"((a)[2]), "r"((a)[3]), "r"(b0), "r"(b1))

// ======================= HMMA fp16 GEMM =======================
// C[M,N] = A[M,K] * B[N,K]^T, A/B fp16 K-major, C f32. K % 32 == 0.
// CTA 128x128, BK=32, 3 stages, 256 threads (8 warps of 64x32).
#define STAGE_BYTES 16384   // A 8KB + B 8KB
#define NSTAGE 3

template<bool BIAS>
__global__ void __launch_bounds__(256, 2) gemm_hmma(
    const __half* __restrict__ A, const __half* __restrict__ B,
    const float* __restrict__ bias, float* __restrict__ C,
    int Mn, int Nn, int Kn)
{
    __shared__ __align__(128) char smem[NSTAGE * STAGE_BYTES];  // 48KB
    const uint32_t sb = smem_u32(smem);
    const int tid = threadIdx.x;
    const int lane = tid & 31, wid = tid >> 5;
    const int warp_m = wid & 1, warp_n = wid >> 1;     // 2 x 4 warp grid
    const int m0 = blockIdx.y * 128, n0 = blockIdx.x * 128;
    const int KT = Kn >> 5;

    const __half* Ag = A + (size_t)m0 * Kn;
    const __half* Bg = B + (size_t)n0 * Kn;

    // precompute per-thread load coords (2 chunks of 16B for A and B each)
    // chunk id -> row = id>>2, c = id&3 ; smem swizzle: c ^= (row>>1)&3
    int l_row[2], l_c[2]; uint32_t l_sw[2];
    #pragma unroll
    for (int h = 0; h < 2; h++) {
        int id = tid + h * 256;
        l_row[h] = id >> 2; l_c[h] = id & 3;
        l_sw[h] = (uint32_t)(l_row[h] * 64 + ((l_c[h] ^ ((l_row[h] >> 1) & 3)) << 4));
    }

    #define LD_STAGE(s, kt) do { \
        uint32_t abase_ = sb + (s) * STAGE_BYTES; \
        uint32_t bbase_ = abase_ + 8192; \
        _Pragma("unroll") \
        for (int h = 0; h < 2; h++) { \
            cp16(abase_ + l_sw[h], Ag + (size_t)l_row[h] * Kn + (kt) * 32 + l_c[h] * 8); \
            cp16(bbase_ + l_sw[h], Bg + (size_t)l_row[h] * Kn + (kt) * 32 + l_c[h] * 8); \
        } \
    } while (0)

    // prologue: stages 0..1
    LD_STAGE(0, 0); CP_COMMIT();
    LD_STAGE(1, 1); CP_COMMIT();

    float acc[4][4][4];
    #pragma unroll
    for (int i = 0; i < 4; i++)
        #pragma unroll
        for (int j = 0; j < 4; j++)
            #pragma unroll
            for (int q = 0; q < 4; q++) acc[i][j][q] = 0.0f;

    // per-lane ldmatrix address components (row-dependent parts)
    const int a_row_l = lane & 15;          // + warp_m*64 + i*16
    const int a_csel  = lane >> 4;          // + 2*k16
    const int b_row_l = ((lane >> 4) << 3) + (lane & 7);  // + warp_n*32 + j*16
    const int b_csel  = (lane >> 3) & 1;    // + 2*k16

    int stage = 0;
    for (int kt = 0; kt < KT; kt++) {
        CP_WAIT1();
        __syncthreads();
        if (kt + 2 < KT) {
            int s2 = stage + 2; if (s2 >= NSTAGE) s2 -= NSTAGE;
            LD_STAGE(s2, kt + 2);
        }
        CP_COMMIT();

        const uint32_t abase = sb + stage * STAGE_BYTES;
        const uint32_t bbase = abase + 8192;

        #pragma unroll
        for (int k16 = 0; k16 < 2; k16++) {
            uint32_t ar[4][4], br[2][4];
            #pragma unroll
            for (int i = 0; i < 4; i++) {
                int row = warp_m * 64 + i * 16 + a_row_l;
                int c = k16 * 2 + a_csel;
                LDSM4(ar[i], abase + row * 64 + ((c ^ ((row >> 1) & 3)) << 4));
            }
            #pragma unroll
            for (int j = 0; j < 2; j++) {
                int row = warp_n * 32 + j * 16 + b_row_l;
                int c = k16 * 2 + b_csel;
                LDSM4(br[j], bbase + row * 64 + ((c ^ ((row >> 1) & 3)) << 4));
            }
            #pragma unroll
            for (int i = 0; i < 4; i++)
                #pragma unroll
                for (int j = 0; j < 4; j++)
                    MMA16816(acc[i][j], ar[i], br[j >> 1][(j & 1) * 2],
                             br[j >> 1][(j & 1) * 2 + 1]);
        }
        if (++stage == NSTAGE) stage = 0;
    }

    // epilogue: direct f32 stores (float2 per fragment row)
    #pragma unroll
    for (int i = 0; i < 4; i++) {
        const int r0 = m0 + warp_m * 64 + i * 16 + (lane >> 2);
        #pragma unroll
        for (int j = 0; j < 4; j++) {
            const int col = n0 + warp_n * 32 + j * 8 + (lane & 3) * 2;
            float2 v0 = make_float2(acc[i][j][0], acc[i][j][1]);
            float2 v1 = make_float2(acc[i][j][2], acc[i][j][3]);
            if (BIAS) {
                float b0v = bias[col], b1v = bias[col + 1];
                v0.x += b0v; v0.y += b1v; v1.x += b0v; v1.y += b1v;
            }
            *reinterpret_cast<float2*>(&C[(size_t)r0 * Nn + col]) = v0;
            *reinterpret_cast<float2*>(&C[(size_t)(r0 + 8) * Nn + col]) = v1;
        }
    }
}

// ======================= conversion kernels =======================
__global__ void f2h_k(const float4* __restrict__ in, __half2* __restrict__ out, int n4) {
    int i = blockIdx.x * blockDim.x + threadIdx.x;
    if (i < n4) {
        float4 v = in[i];
        out[2 * i]     = __floats2half2_rn(v.x, v.y);
        out[2 * i + 1] = __floats2half2_rn(v.z, v.w);
    }
}

// in [R, Cc] f32 row-major -> out [Cc, R] fp16 row-major
__global__ void transpose_h_k(const float* __restrict__ in, __half* __restrict__ out,
                              int R, int Cc) {
    __shared__ float t[32][33];
    const int bx = blockIdx.x * 32;   // col block in 'in'
    const int by = blockIdx.y * 32;   // row block in 'in'
    const int tx = threadIdx.x, ty = threadIdx.y;
#pragma unroll
    for (int j = 0; j < 32; j += 8)
        t[ty + j][tx] = in[(size_t)(by + ty + j) * Cc + bx + tx];
    __syncthreads();
#pragma unroll
    for (int j = 0; j < 32; j += 8)
        out[(size_t)(bx + ty + j) * R + by + tx] = __float2half_rn(t[tx][ty + j]);
}

// ======================= per-batch attention kernel =======================
__global__ void __launch_bounds__(512) attn_kernel(
    const float* __restrict__ qkv,
    const float* __restrict__ W_E, const float* __restrict__ W_F,
    __half* __restrict__ ho, float* __restrict__ sel_out)
{
    __shared__ float s[SEQ * QKVC];  // 48 KB
    const int b = blockIdx.x;
    const int tid = threadIdx.x;

    const float4* src = reinterpret_cast<const float4*>(qkv + (size_t)b * SEQ * QKVC);
    float4* dst = reinterpret_cast<float4*>(s);
#pragma unroll
    for (int i = 0; i < 6; i++) dst[tid + i * 512] = src[tid + i * 512];
    __syncthreads();

    const int h = tid >> 5, lane = tid & 31;
    const int d0 = lane << 1;

    float q[SEQ][2], kk[SEQ][2], vv[SEQ][2];
#pragma unroll
    for (int n = 0; n < SEQ; n++) {
#pragma unroll
        for (int j = 0; j < 2; j++) {
            q[n][j]  = s[n * QKVC +            h * HDIM + d0 + j] * 0.125f;
            kk[n][j] = s[n * QKVC + CDIM +     h * HDIM + d0 + j];
            vv[n][j] = s[n * QKVC + 2 * CDIM + h * HDIM + d0 + j];
        }
    }

    float wE[16], wF[16];
#pragma unroll
    for (int i = 0; i < 16; i++) { wE[i] = __ldg(&W_E[i]); wF[i] = __ldg(&W_F[i]); }

    float klow[PDIM][2], vlow[PDIM][2];
#pragma unroll
    for (int p = 0; p < PDIM; p++)
#pragma unroll
        for (int j = 0; j < 2; j++) {
            klow[p][j] = wE[p*4+0]*kk[0][j] + wE[p*4+1]*kk[1][j]
                       + wE[p*4+2]*kk[2][j] + wE[p*4+3]*kk[3][j];
            vlow[p][j] = wF[p*4+0]*vv[0][j] + wF[p*4+1]*vv[1][j]
                       + wF[p*4+2]*vv[2][j] + wF[p*4+3]*vv[3][j];
        }

    float attn[SEQ][PDIM];
#pragma unroll
    for (int n = 0; n < SEQ; n++)
#pragma unroll
        for (int p = 0; p < PDIM; p++) {
            float part = q[n][0]*klow[p][0] + q[n][1]*klow[p][1];
#pragma unroll
            for (int o = 16; o > 0; o >>= 1)
                part += __shfl_xor_sync(0xffffffffu, part, o);
            attn[n][p] = part;
        }

#pragma unroll
    for (int n = 0; n < SEQ; n++) {
        float mx = fmaxf(fmaxf(attn[n][0], attn[n][1]), fmaxf(attn[n][2], attn[n][3]));
        float e0 = expf(attn[n][0]-mx), e1 = expf(attn[n][1]-mx);
        float e2 = expf(attn[n][2]-mx), e3 = expf(attn[n][3]-mx);
        float inv = 1.0f / (e0 + e1 + e2 + e3);
        attn[n][0] = e0*inv; attn[n][1] = e1*inv; attn[n][2] = e2*inv; attn[n][3] = e3*inv;
    }

#pragma unroll
    for (int n = 0; n < SEQ; n++) {
        float o0 = attn[n][0]*vlow[0][0] + attn[n][1]*vlow[1][0]
                 + attn[n][2]*vlow[2][0] + attn[n][3]*vlow[3][0];
        float o1 = attn[n][0]*vlow[0][1] + attn[n][1]*vlow[1][1]
                 + attn[n][2]*vlow[2][1] + attn[n][3]*vlow[3][1];
        *reinterpret_cast<__half2*>(
            &ho[(size_t)(b * SEQ + n) * CDIM + h * HDIM + d0]) =
            __floats2half2_rn(o0, o1);
    }

    float selval = 0.0f;
#pragma unroll
    for (int g = 0; g < HEADS; g++) {
        float part = q[1][0] * s[2*QKVC + CDIM + g*HDIM + d0]
                   + q[1][1] * s[2*QKVC + CDIM + g*HDIM + d0 + 1];
#pragma unroll
        for (int o = 16; o > 0; o >>= 1)
            part += __shfl_xor_sync(0xffffffffu, part, o);
        if (lane == g) selval = part;
    }
    if (lane < HEADS)
        sel_out[(size_t)b * HEADS * HEADS + h * HEADS + lane] =
            1.0f / (1.0f + expf(-selval));
}

// ======================= launch =======================
extern "C" void kernel_launch(void* const* d_in, const int* in_sizes, int n_in,
                              void* d_out, int out_size) {
    const float* x      = (const float*)d_in[0];
    const float* W_qkv  = (const float*)d_in[1];
    const float* W_proj = (const float*)d_in[2];
    const float* b_proj = (const float*)d_in[3];
    const float* W_E    = (const float*)d_in[4];
    const float* W_F    = (const float*)d_in[5];
    float* out = (float*)d_out;
    float* sel = out + OUT_ELEMS;

    static __half *xh = nullptr, *wqh = nullptr, *wph = nullptr, *hoh = nullptr;
    static float *qkv = nullptr;
    if (!xh) {
        cudaGetSymbolAddress((void**)&xh,  g_xh);
        cudaGetSymbolAddress((void**)&wqh, g_wqh);
        cudaGetSymbolAddress((void**)&wph, g_wph);
        cudaGetSymbolAddress((void**)&hoh, g_hoh);
        cudaGetSymbolAddress((void**)&qkv, g_qkv);
    }

    // conversions
    f2h_k<<<(OUT_ELEMS / 4 + 255) / 256, 256>>>(
        (const float4*)x, (__half2*)xh, (int)(OUT_ELEMS / 4));
    transpose_h_k<<<dim3(QKVC / 32, CDIM / 32), dim3(32, 8)>>>(
        W_qkv, wqh, CDIM, QKVC);
    f2h_k<<<(CDIM * CDIM / 4 + 255) / 256, 256>>>(
        (const float4*)W_proj, (__half2*)wph, CDIM * CDIM / 4);

    // 1) qkv = x @ W_qkv
    gemm_hmma<false><<<dim3(QKVC / 128, MROWS / 128), 256>>>(
        xh, wqh, nullptr, qkv, MROWS, QKVC, CDIM);
    // 2) attention middle + sel gate (fp32 math, fp16 output for GEMM2)
    attn_kernel<<<BATCH, 512>>>(qkv, W_E, W_F, hoh, sel);
    // 3) out = ho @ W_proj^T + b_proj
    gemm_hmma<true><<<dim3(CDIM / 128, MROWS / 128), 256>>>(
        hoh, wph, b_proj, out, MROWS, CDIM, CDIM);
}